// round 13
// baseline (speedup 1.0000x reference)
#include <cuda_runtime.h>
#include <cuda_bf16.h>
#include <math.h>

// Problem constants
#define Lc 4
#define Bc 16
#define Sc 512
#define Hc 768
#define NHc 12
#define FFc 3072
#define Dc 64
#define Mrows (Bc*Sc)          // 8192
#define BHc (Bc*NHc)           // 192
#define QKVS 2304              // packed qkv row stride

// ---------------- scratch (device globals; no allocations allowed) -------------
__device__ float g_h [Mrows*Hc];
__device__ float g_y [Mrows*Hc];
__device__ float g_ao[Mrows*Hc];
__device__ float g_sc[(size_t)BHc*Sc*Sc];   // 201 MB
__device__ float g_ff[(size_t)Mrows*FFc];   // 100 MB (holds packed qkv early in layer)
__device__ float g_wqkvT[(size_t)Lc*3*Hc*Hc];  // [L][2304][768]
__device__ float g_woT  [(size_t)Lc*Hc*Hc];    // [L][768][768]
__device__ float g_w1T  [(size_t)Lc*FFc*Hc];   // [L][3072][768]
__device__ float g_w2T  [(size_t)Lc*Hc*FFc];   // [L][768][3072]
__device__ float g_bqkv [Lc*3*Hc];

// ---------------- reductions -------------
__device__ __forceinline__ float warpSum(float v){
#pragma unroll
    for (int o=16;o>0;o>>=1) v += __shfl_xor_sync(0xffffffffu, v, o);
    return v;
}
__device__ __forceinline__ float warpMax(float v){
#pragma unroll
    for (int o=16;o>0;o>>=1) v = fmaxf(v, __shfl_xor_sync(0xffffffffu, v, o));
    return v;
}
__device__ float blockSum(float v){
    __shared__ float sh[8];
    __syncthreads();
    v = warpSum(v);
    int lane = threadIdx.x & 31, w = threadIdx.x >> 5;
    if (lane==0) sh[w] = v;
    __syncthreads();
    int nw = blockDim.x >> 5;
    float r = 0.f;
#pragma unroll 8
    for (int i=0;i<nw;i++) if (i < nw) r += sh[i];
    return r;
}
__device__ float blockMax(float v){
    __shared__ float sh[8];
    __syncthreads();
    v = warpMax(v);
    int lane = threadIdx.x & 31, w = threadIdx.x >> 5;
    if (lane==0) sh[w] = v;
    __syncthreads();
    int nw = blockDim.x >> 5;
    float r = -3.402823466e38f;
#pragma unroll 8
    for (int i=0;i<nw;i++) if (i < nw) r = fmaxf(r, sh[i]);
    return r;
}

// ---------------- helpers -------------
__device__ __forceinline__ unsigned f2tf32(float x){
    unsigned r; asm("cvt.rna.tf32.f32 %0, %1;" : "=r"(r) : "f"(x)); return r;
}
__device__ __forceinline__ float tf32f(float x){
    return __uint_as_float(f2tf32(x));
}
__device__ __forceinline__ void ldsm4(unsigned* d, const float* p){
    unsigned a = (unsigned)__cvta_generic_to_shared(p);
    asm volatile("ldmatrix.sync.aligned.m8n8.x4.shared.b16 {%0,%1,%2,%3}, [%4];"
                 : "=r"(d[0]),"=r"(d[1]),"=r"(d[2]),"=r"(d[3]) : "r"(a));
}
__device__ __forceinline__ void mma_tf32(float* c, const unsigned* a, unsigned b0, unsigned b1){
    asm volatile("mma.sync.aligned.m16n8k8.row.col.f32.tf32.tf32.f32 "
                 "{%0,%1,%2,%3}, {%4,%5,%6,%7}, {%8,%9}, {%0,%1,%2,%3};"
                 : "+f"(c[0]),"+f"(c[1]),"+f"(c[2]),"+f"(c[3])
                 : "r"(a[0]),"r"(a[1]),"r"(a[2]),"r"(a[3]), "r"(b0),"r"(b1));
}
__device__ __forceinline__ float gelu_exact(float x){
    return 0.5f * x * (1.0f + erff(x * 0.70710678118654752f));
}
__device__ __forceinline__ void cpa16(unsigned dst, const void* src){
    asm volatile("cp.async.cg.shared.global [%0], [%1], 16;" :: "r"(dst), "l"(src));
}
__device__ __forceinline__ void cpa_commit(){
    asm volatile("cp.async.commit_group;" ::: "memory");
}
template<int W> __device__ __forceinline__ void cpa_wait(){
    asm volatile("cp.async.wait_group %0;" :: "n"(W) : "memory");
}

// ---------------- LayerNorm (rnd: tf32-round output for GEMM A operands) ----
__global__ void ln_kernel(const float* __restrict__ x, const float* __restrict__ g,
                          const float* __restrict__ b, float* __restrict__ o, int rnd){
    int row = blockIdx.x;
    const float* p = x + (size_t)row*Hc;
    int t = threadIdx.x;
    float v0 = p[t], v1 = p[t+256], v2 = p[t+512];
    float s  = blockSum(v0+v1+v2);
    float m  = s * (1.0f/768.0f);
    float d0 = v0-m, d1 = v1-m, d2 = v2-m;
    float vs = blockSum(d0*d0 + d1*d1 + d2*d2);
    float inv = rsqrtf(vs * (1.0f/768.0f) + 1e-5f);
    float* q = o + (size_t)row*Hc;
    float r0 = d0*inv*g[t]     + b[t];
    float r1 = d1*inv*g[t+256] + b[t+256];
    float r2 = d2*inv*g[t+512] + b[t+512];
    if (rnd){ r0 = tf32f(r0); r1 = tf32f(r1); r2 = tf32f(r2); }
    q[t] = r0; q[t+256] = r1; q[t+512] = r2;
}

// ---------------- weight transpose + tf32 round ----
__global__ void transpose_w(const float* __restrict__ in, float* __restrict__ out,
                            int K, int N, int noff, int OS,
                            size_t inL, size_t outL){
    __shared__ float t[32][33];
    int l = blockIdx.z;
    in  += (size_t)l*inL;
    out += (size_t)l*outL;
    int nb = blockIdx.x*32, kb = blockIdx.y*32;
    int tx = threadIdx.x, ty = threadIdx.y;   // 32 x 8
#pragma unroll
    for (int j=0;j<4;j++)
        t[ty+j*8][tx] = in[(size_t)(kb+ty+j*8)*N + nb+tx];
    __syncthreads();
#pragma unroll
    for (int j=0;j<4;j++)
        out[(size_t)(noff+nb+ty+j*8)*OS + kb+tx] = tf32f(t[tx][ty+j*8]);
}

// ---------------- pack qkv bias ----
__global__ void pack_bias(const float* __restrict__ bq, const float* __restrict__ bk,
                          const float* __restrict__ bv, float* __restrict__ o){
    int i = blockIdx.x*256 + threadIdx.x;
    if (i < Lc*QKVS){
        int l = i/QKVS, j = i%QKVS;
        float v = (j<768) ? bq[l*768+j] : (j<1536 ? bk[l*768+j-768] : bv[l*768+j-1536]);
        o[i] = v;
    }
}

// ---------------- cp.async tf32 GEMM: 128x128 tile, warp 64x32 (for N=768 GEMMs) ----
#define PADt 20
#define STGF (128*PADt)
#define CPG_SMEM (3*2*STGF*4)   // 61440 B
template<int EPI>
__global__ __launch_bounds__(256,2) void cp_gemm(
        const float* __restrict__ A, const float* __restrict__ Bt,
        const float* __restrict__ bias, const float* __restrict__ R,
        float* __restrict__ C, int K, int N){
    extern __shared__ float sms[];
    int tid = threadIdx.x;
    int bm = blockIdx.y*128, bn = blockIdx.x*128;
    int warp = tid>>5, lane = tid&31;
    int wm = (warp>>2)*64, wn = (warp&3)*32;

    int id0 = tid*2, id1 = tid*2+1;
    int r0 = id0>>2, s0g = id0&3, r1 = id1>>2, s1g = id1&3;
    const float* Ap0 = A + (size_t)(bm+r0)*K + s0g*4;
    const float* Ap1 = A + (size_t)(bm+r1)*K + s1g*4;
    const float* Bp0 = Bt + (size_t)(bn+r0)*K + s0g*4;
    const float* Bp1 = Bt + (size_t)(bn+r1)*K + s1g*4;
    unsigned sbase = (unsigned)__cvta_generic_to_shared(sms);
    unsigned oa0 = (r0*PADt + s0g*4)*4, oa1 = (r1*PADt + s1g*4)*4;

    int g = lane>>3, lr = lane&7;
    int a_row = wm + lr + (g&1)*8;
    int a_colq = (g>>1)*4;
    int b_row = wn + lr + (g>>1)*8;
    int b_colq = (g&1)*4;

    float acc[16][4];
#pragma unroll
    for (int i=0;i<16;i++){ acc[i][0]=0.f; acc[i][1]=0.f; acc[i][2]=0.f; acc[i][3]=0.f; }

    int nch = K >> 4;
#pragma unroll
    for (int st=0; st<2; st++){
        unsigned base = sbase + st*(2*STGF*4);
        int k0 = st*16;
        cpa16(base + oa0, Ap0 + k0);
        cpa16(base + oa1, Ap1 + k0);
        cpa16(base + STGF*4 + oa0, Bp0 + k0);
        cpa16(base + STGF*4 + oa1, Bp1 + k0);
        cpa_commit();
    }

#pragma unroll 1
    for (int it=0; it<nch; ++it){
        int st = it - (it/3)*3;
        if (it+2 < nch) cpa_wait<1>(); else cpa_wait<0>();
        __syncthreads();
        const float* as = sms + st*(2*STGF);
        const float* bs = as + STGF;
#pragma unroll
        for (int kc=0; kc<16; kc+=8){
            unsigned af[4][4];
#pragma unroll
            for (int mt=0; mt<4; mt++)
                ldsm4(af[mt], &as[(a_row + mt*16)*PADt + kc + a_colq]);
            unsigned bf[2][4];
#pragma unroll
            for (int np=0; np<2; np++)
                ldsm4(bf[np], &bs[(b_row + np*16)*PADt + kc + b_colq]);
#pragma unroll
            for (int mt=0; mt<4; mt++)
#pragma unroll
                for (int nt=0; nt<4; nt++)
                    mma_tf32(acc[mt*4+nt], af[mt], bf[nt>>1][(nt&1)*2], bf[nt>>1][(nt&1)*2+1]);
        }
        if (it+2 < nch){
            int st2 = (it+2) - ((it+2)/3)*3;
            unsigned base = sbase + st2*(2*STGF*4);
            int k0 = (it+2)*16;
            cpa16(base + oa0, Ap0 + k0);
            cpa16(base + oa1, Ap1 + k0);
            cpa16(base + STGF*4 + oa0, Bp0 + k0);
            cpa16(base + STGF*4 + oa1, Bp1 + k0);
            cpa_commit();
        }
    }

    int cr = lane>>2, cc = (lane&3)*2;
#pragma unroll
    for (int nt=0; nt<4; nt++){
        int col = bn + wn + nt*8 + cc;
        float2 bv = *(const float2*)(bias + col);
#pragma unroll
        for (int mt=0; mt<4; mt++){
            int row0 = bm + wm + mt*16 + cr;
            float* a4 = acc[mt*4+nt];
#pragma unroll
            for (int half=0; half<2; half++){
                int row = row0 + half*8;
                float2 r;
                r.x = a4[half*2+0] + bv.x;
                r.y = a4[half*2+1] + bv.y;
                if (EPI==1){
                    r.x = tf32f(gelu_exact(r.x));
                    r.y = tf32f(gelu_exact(r.y));
                }
                if (EPI==2){
                    float2 rr = *(const float2*)(R + (size_t)row*N + col);
                    r.x += rr.x; r.y += rr.y;
                }
                *(float2*)(C + (size_t)row*N + col) = r;
            }
        }
    }
}

// ---------------- cp.async tf32 GEMM: 128x256 tile, warp 64x64 (QKV/FFN1) ----
// 8 warps as 2(m) x 4(n). acc = 128 regs/thread, occupancy 1.
#define STGA (128*PADt)
#define STGB (256*PADt)
#define STG256 (STGA+STGB)
#define CPG256_SMEM (3*STG256*4)   // 92160 B
template<int EPI>
__global__ __launch_bounds__(256) void cp_gemm256(
        const float* __restrict__ A, const float* __restrict__ Bt,
        const float* __restrict__ bias,
        float* __restrict__ C, int K, int N){
    extern __shared__ float sms[];
    int tid = threadIdx.x;
    int bm = blockIdx.y*128, bn = blockIdx.x*256;
    int warp = tid>>5, lane = tid&31;
    int wm = (warp>>2)*64, wn = (warp&3)*64;

    // A cp.async: 2 ops/thread
    int id0 = tid*2, id1 = tid*2+1;
    int r0 = id0>>2, s0g = id0&3, r1 = id1>>2, s1g = id1&3;
    const float* Ap0 = A + (size_t)(bm+r0)*K + s0g*4;
    const float* Ap1 = A + (size_t)(bm+r1)*K + s1g*4;
    // B cp.async: thread owns row (bn+tid), all 4 segs
    const float* Bp = Bt + (size_t)(bn+tid)*K;
    unsigned sbase = (unsigned)__cvta_generic_to_shared(sms);
    unsigned oa0 = (r0*PADt + s0g*4)*4, oa1 = (r1*PADt + s1g*4)*4;
    unsigned ob  = (STGA + tid*PADt)*4;

    int g = lane>>3, lr = lane&7;
    int a_row = wm + lr + (g&1)*8;
    int a_colq = (g>>1)*4;
    int b_row = wn + lr + (g>>1)*8;
    int b_colq = (g&1)*4;

    float acc[32][4];
#pragma unroll
    for (int i=0;i<32;i++){ acc[i][0]=0.f; acc[i][1]=0.f; acc[i][2]=0.f; acc[i][3]=0.f; }

    int nch = K >> 4;
#pragma unroll
    for (int st=0; st<2; st++){
        unsigned base = sbase + st*(STG256*4);
        int k0 = st*16;
        cpa16(base + oa0, Ap0 + k0);
        cpa16(base + oa1, Ap1 + k0);
#pragma unroll
        for (int j=0;j<4;j++) cpa16(base + ob + j*16, Bp + k0 + j*4);
        cpa_commit();
    }

#pragma unroll 1
    for (int it=0; it<nch; ++it){
        int st = it - (it/3)*3;
        if (it+2 < nch) cpa_wait<1>(); else cpa_wait<0>();
        __syncthreads();
        const float* as = sms + st*STG256;
        const float* bs = as + STGA;
#pragma unroll
        for (int kc=0; kc<16; kc+=8){
            unsigned af[4][4];
#pragma unroll
            for (int mt=0; mt<4; mt++)
                ldsm4(af[mt], &as[(a_row + mt*16)*PADt + kc + a_colq]);
            unsigned bf[4][4];
#pragma unroll
            for (int np=0; np<4; np++)
                ldsm4(bf[np], &bs[(b_row + np*16)*PADt + kc + b_colq]);
#pragma unroll
            for (int mt=0; mt<4; mt++)
#pragma unroll
                for (int nt=0; nt<8; nt++)
                    mma_tf32(acc[mt*8+nt], af[mt], bf[nt>>1][(nt&1)*2], bf[nt>>1][(nt&1)*2+1]);
        }
        if (it+2 < nch){
            int st2 = (it+2) - ((it+2)/3)*3;
            unsigned base = sbase + st2*(STG256*4);
            int k0 = (it+2)*16;
            cpa16(base + oa0, Ap0 + k0);
            cpa16(base + oa1, Ap1 + k0);
#pragma unroll
            for (int j=0;j<4;j++) cpa16(base + ob + j*16, Bp + k0 + j*4);
            cpa_commit();
        }
    }

    int cr = lane>>2, cc = (lane&3)*2;
#pragma unroll
    for (int nt=0; nt<8; nt++){
        int col = bn + wn + nt*8 + cc;
        float2 bv = *(const float2*)(bias + col);
#pragma unroll
        for (int mt=0; mt<4; mt++){
            int row0 = bm + wm + mt*16 + cr;
            float* a4 = acc[mt*8+nt];
#pragma unroll
            for (int half=0; half<2; half++){
                int row = row0 + half*8;
                float2 r;
                r.x = a4[half*2+0] + bv.x;
                r.y = a4[half*2+1] + bv.y;
                if (EPI==1){
                    r.x = tf32f(gelu_exact(r.x));
                    r.y = tf32f(gelu_exact(r.y));
                }
                *(float2*)(C + (size_t)row*N + col) = r;
            }
        }
    }
}

// ---------------- tf32 QK^T: 128x128 tile, K=64, fused scale+bias ----
#define PADQ 68
__global__ __launch_bounds__(256,2) void attn_qk_mma(
        const float* __restrict__ q, const float* __restrict__ k,
        const float* __restrict__ bias, float* __restrict__ sc){
    extern __shared__ float sm[];
    float* Qs = sm;
    float* Ks = sm + 128*PADQ;
    int bh = blockIdx.z;
    int b = bh / NHc, h = bh % NHc;
    int s0 = blockIdx.y*128, t0 = blockIdx.x*128;
    int tid = threadIdx.x;
    int warp = tid>>5, lane = tid&31;
    int wm = (warp>>2)*64, wn = (warp&3)*32;

    {
        int row = tid>>1, cb = (tid&1)*32;
        const float* qp = q + (size_t)(b*Sc + s0 + row)*QKVS + h*Dc + cb;
        const float* kp = k + (size_t)(b*Sc + t0 + row)*QKVS + h*Dc + cb;
        float* dq = &Qs[row*PADQ + cb];
        float* dk = &Ks[row*PADQ + cb];
#pragma unroll
        for (int z=0; z<8; z++){
            float4 a = *(const float4*)(qp + z*4);
            dq[z*4+0]=tf32f(a.x); dq[z*4+1]=tf32f(a.y);
            dq[z*4+2]=tf32f(a.z); dq[z*4+3]=tf32f(a.w);
            float4 c = *(const float4*)(kp + z*4);
            dk[z*4+0]=tf32f(c.x); dk[z*4+1]=tf32f(c.y);
            dk[z*4+2]=tf32f(c.z); dk[z*4+3]=tf32f(c.w);
        }
    }
    __syncthreads();

    int g = lane>>3, lr = lane&7;
    int a_row = wm + lr + (g&1)*8;
    int a_colq = (g>>1)*4;
    int b_row = wn + lr + (g>>1)*8;
    int b_colq = (g&1)*4;

    float acc[16][4];
#pragma unroll
    for (int i=0;i<16;i++){ acc[i][0]=0.f; acc[i][1]=0.f; acc[i][2]=0.f; acc[i][3]=0.f; }

#pragma unroll
    for (int kc=0; kc<64; kc+=8){
        unsigned af[4][4];
#pragma unroll
        for (int mt=0; mt<4; mt++)
            ldsm4(af[mt], &Qs[(a_row + mt*16)*PADQ + kc + a_colq]);
        unsigned bf[2][4];
#pragma unroll
        for (int np=0; np<2; np++)
            ldsm4(bf[np], &Ks[(b_row + np*16)*PADQ + kc + b_colq]);
#pragma unroll
        for (int mt=0; mt<4; mt++)
#pragma unroll
            for (int nt=0; nt<4; nt++)
                mma_tf32(acc[mt*4+nt], af[mt], bf[nt>>1][(nt&1)*2], bf[nt>>1][(nt&1)*2+1]);
    }

    int cr = lane>>2, cc = (lane&3)*2;
#pragma unroll
    for (int nt=0; nt<4; nt++){
        int tcol = t0 + wn + nt*8 + cc;
#pragma unroll
        for (int mt=0; mt<4; mt++){
            float* a4 = acc[mt*4+nt];
#pragma unroll
            for (int half=0; half<2; half++){
                int srow = s0 + wm + mt*16 + cr + half*8;
                size_t idx = ((size_t)bh*Sc + srow)*Sc + tcol;
                float2 bi = *(const float2*)(bias + idx);
                float2 r;
                r.x = fmaf(a4[half*2+0], 0.125f, bi.x);
                r.y = fmaf(a4[half*2+1], 0.125f, bi.y);
                *(float2*)(sc + idx) = r;
            }
        }
    }
}

// ---------------- softmax -------------
__global__ void softmax_kernel(float* __restrict__ sc){
    size_t row = blockIdx.x;
    float* p = sc + row*Sc;
    int t = threadIdx.x;
    float v[4];
#pragma unroll
    for (int i=0;i<4;i++) v[i] = p[t + i*128];
    float mx = fmaxf(fmaxf(v[0],v[1]), fmaxf(v[2],v[3]));
    mx = blockMax(mx);
    float s = 0.f;
#pragma unroll
    for (int i=0;i<4;i++){ v[i] = __expf(v[i]-mx); s += v[i]; }
    s = blockSum(s);
    float r = 1.0f / s;
#pragma unroll
    for (int i=0;i<4;i++) p[t + i*128] = v[i]*r;
}

// ---------------- tf32 A@V: 128(s) x 64(d), K=512 in chunks of 64 ----
__global__ __launch_bounds__(256,2) void attn_av_mma(
        const float* __restrict__ sc, const float* __restrict__ v,
        float* __restrict__ o){
    extern __shared__ float sm[];
    float* As = sm;
    float* Vs = sm + 128*PADQ;
    int bh = blockIdx.y;
    int b = bh / NHc, h = bh % NHc;
    int s0 = blockIdx.x*128;
    int tid = threadIdx.x;
    int warp = tid>>5, lane = tid&31;
    int wm = (warp>>1)*32, wn = (warp&1)*32;

    int g = lane>>3, lr = lane&7;
    int a_row = wm + lr + (g&1)*8;
    int a_colq = (g>>1)*4;
    int b_row = wn + lr + (g>>1)*8;
    int b_colq = (g&1)*4;

    float acc[8][4];
#pragma unroll
    for (int i=0;i<8;i++){ acc[i][0]=0.f; acc[i][1]=0.f; acc[i][2]=0.f; acc[i][3]=0.f; }

    int prow = tid>>1, pcb = (tid&1)*32;
    int vt = tid>>2, vdb = (tid&3)*16;

    for (int t0c=0; t0c<Sc; t0c+=64){
        const float* pp = sc + ((size_t)bh*Sc + (s0+prow))*Sc + t0c + pcb;
        const float* vp = v + (size_t)(b*Sc + t0c + vt)*QKVS + h*Dc + vdb;
        float4 pv[8], vv[4];
#pragma unroll
        for (int z=0; z<8; z++) pv[z] = *(const float4*)(pp + z*4);
#pragma unroll
        for (int z=0; z<4; z++) vv[z] = *(const float4*)(vp + z*4);
        __syncthreads();
        float* dp = &As[prow*PADQ + pcb];
#pragma unroll
        for (int z=0; z<8; z++){
            dp[z*4+0]=tf32f(pv[z].x); dp[z*4+1]=tf32f(pv[z].y);
            dp[z*4+2]=tf32f(pv[z].z); dp[z*4+3]=tf32f(pv[z].w);
        }
#pragma unroll
        for (int z=0; z<4; z++){
            Vs[(vdb+z*4+0)*PADQ + vt]=tf32f(vv[z].x);
            Vs[(vdb+z*4+1)*PADQ + vt]=tf32f(vv[z].y);
            Vs[(vdb+z*4+2)*PADQ + vt]=tf32f(vv[z].z);
            Vs[(vdb+z*4+3)*PADQ + vt]=tf32f(vv[z].w);
        }
        __syncthreads();
#pragma unroll
        for (int kc=0; kc<64; kc+=8){
            unsigned af[2][4];
#pragma unroll
            for (int mt=0; mt<2; mt++)
                ldsm4(af[mt], &As[(a_row + mt*16)*PADQ + kc + a_colq]);
            unsigned bf[2][4];
#pragma unroll
            for (int np=0; np<2; np++)
                ldsm4(bf[np], &Vs[(b_row + np*16)*PADQ + kc + b_colq]);
#pragma unroll
            for (int mt=0; mt<2; mt++)
#pragma unroll
                for (int nt=0; nt<4; nt++)
                    mma_tf32(acc[mt*4+nt], af[mt], bf[nt>>1][(nt&1)*2], bf[nt>>1][(nt&1)*2+1]);
        }
    }

    int cr = lane>>2, cc = (lane&3)*2;
#pragma unroll
    for (int nt=0; nt<4; nt++){
        int dcol = wn + nt*8 + cc;
#pragma unroll
        for (int mt=0; mt<2; mt++){
            float* a4 = acc[mt*4+nt];
#pragma unroll
            for (int half=0; half<2; half++){
                int srow = s0 + wm + mt*16 + cr + half*8;
                float2 r;
                r.x = tf32f(a4[half*2+0]);
                r.y = tf32f(a4[half*2+1]);
                *(float2*)(o + ((size_t)(b*Sc + srow)*NHc + h)*Dc + dcol) = r;
            }
        }
    }
}

// ---------------- launch -------------
extern "C" void kernel_launch(void* const* d_in, const int* in_sizes, int n_in,
                              void* d_out, int out_size){
    const float* x    = (const float*)d_in[0];
    const float* ab   = (const float*)d_in[1];
    const float* ln1g = (const float*)d_in[2];
    const float* ln1b = (const float*)d_in[3];
    const float* wq   = (const float*)d_in[4];
    const float* bq   = (const float*)d_in[5];
    const float* wk   = (const float*)d_in[6];
    const float* bk   = (const float*)d_in[7];
    const float* wv   = (const float*)d_in[8];
    const float* bv   = (const float*)d_in[9];
    const float* wo   = (const float*)d_in[10];
    const float* bo   = (const float*)d_in[11];
    const float* ln2g = (const float*)d_in[12];
    const float* ln2b = (const float*)d_in[13];
    const float* w1   = (const float*)d_in[14];
    const float* b1   = (const float*)d_in[15];
    const float* w2   = (const float*)d_in[16];
    const float* b2   = (const float*)d_in[17];
    const float* flng = (const float*)d_in[18];
    const float* flnb = (const float*)d_in[19];

    float *ph, *py, *pao, *psc, *pff, *pwqkv, *pwo, *pw1, *pw2, *pbqkv;
    cudaGetSymbolAddress((void**)&ph,   g_h);
    cudaGetSymbolAddress((void**)&py,   g_y);
    cudaGetSymbolAddress((void**)&pao,  g_ao);
    cudaGetSymbolAddress((void**)&psc,  g_sc);
    cudaGetSymbolAddress((void**)&pff,  g_ff);
    cudaGetSymbolAddress((void**)&pwqkv,g_wqkvT);
    cudaGetSymbolAddress((void**)&pwo,  g_woT);
    cudaGetSymbolAddress((void**)&pw1,  g_w1T);
    cudaGetSymbolAddress((void**)&pw2,  g_w2T);
    cudaGetSymbolAddress((void**)&pbqkv,g_bqkv);

    static int smem_set = 0;
    const int qk_smem = 2*128*PADQ*sizeof(float);          // 69632
    const int av_smem = (128+64)*PADQ*sizeof(float);       // 52224
    if (!smem_set){
        cudaFuncSetAttribute(attn_qk_mma, cudaFuncAttributeMaxDynamicSharedMemorySize, qk_smem);
        cudaFuncSetAttribute(attn_av_mma, cudaFuncAttributeMaxDynamicSharedMemorySize, av_smem);
        cudaFuncSetAttribute(cp_gemm<0>, cudaFuncAttributeMaxDynamicSharedMemorySize, CPG_SMEM);
        cudaFuncSetAttribute(cp_gemm<1>, cudaFuncAttributeMaxDynamicSharedMemorySize, CPG_SMEM);
        cudaFuncSetAttribute(cp_gemm<2>, cudaFuncAttributeMaxDynamicSharedMemorySize, CPG_SMEM);
        cudaFuncSetAttribute(cp_gemm256<0>, cudaFuncAttributeMaxDynamicSharedMemorySize, CPG256_SMEM);
        cudaFuncSetAttribute(cp_gemm256<1>, cudaFuncAttributeMaxDynamicSharedMemorySize, CPG256_SMEM);
        smem_set = 1;
    }

    cudaMemcpyAsync(ph, x, (size_t)Mrows*Hc*sizeof(float), cudaMemcpyDeviceToDevice, 0);

    // ---- weight prep ----
    dim3 tb(32,8);
    transpose_w<<<dim3(Hc/32, Hc/32, Lc), tb>>>(wq, pwqkv, Hc, Hc, 0,    Hc, (size_t)Hc*Hc, (size_t)QKVS*Hc);
    transpose_w<<<dim3(Hc/32, Hc/32, Lc), tb>>>(wk, pwqkv, Hc, Hc, 768,  Hc, (size_t)Hc*Hc, (size_t)QKVS*Hc);
    transpose_w<<<dim3(Hc/32, Hc/32, Lc), tb>>>(wv, pwqkv, Hc, Hc, 1536, Hc, (size_t)Hc*Hc, (size_t)QKVS*Hc);
    transpose_w<<<dim3(Hc/32, Hc/32, Lc), tb>>>(wo, pwo,   Hc, Hc, 0,    Hc, (size_t)Hc*Hc, (size_t)Hc*Hc);
    transpose_w<<<dim3(FFc/32, Hc/32, Lc), tb>>>(w1, pw1,  Hc, FFc, 0,   Hc, (size_t)Hc*FFc, (size_t)FFc*Hc);
    transpose_w<<<dim3(Hc/32, FFc/32, Lc), tb>>>(w2, pw2,  FFc, Hc, 0,  FFc, (size_t)FFc*Hc, (size_t)Hc*FFc);
    pack_bias<<<(Lc*QKVS+255)/256, 256>>>(bq, bk, bv, pbqkv);

    dim3 gqkv(QKVS/256, Mrows/128);     // 9 x 64
    dim3 gproj(Hc/128, Mrows/128);      // 6 x 64
    dim3 gffn1(FFc/256, Mrows/128);     // 12 x 64
    dim3 gqk(4, 4, BHc);
    dim3 gav(4, BHc);

    for (int l=0; l<Lc; l++){
        ln_kernel<<<Mrows, 256>>>(ph, ln1g + l*Hc, ln1b + l*Hc, py, 1);
        cp_gemm256<0><<<gqkv, 256, CPG256_SMEM>>>(py, pwqkv + (size_t)l*QKVS*Hc, pbqkv + l*QKVS,
                                                  pff, Hc, QKVS);
        attn_qk_mma<<<gqk, 256, qk_smem>>>(pff, pff + 768, ab, psc);
        softmax_kernel<<<BHc*Sc, 128>>>(psc);
        attn_av_mma<<<gav, 256, av_smem>>>(psc, pff + 1536, pao);
        cp_gemm<2><<<gproj, 256, CPG_SMEM>>>(pao, pwo + (size_t)l*Hc*Hc, bo + l*Hc,
                                             ph, ph, Hc, Hc);
        ln_kernel<<<Mrows, 256>>>(ph, ln2g + l*Hc, ln2b + l*Hc, py, 1);
        cp_gemm256<1><<<gffn1, 256, CPG256_SMEM>>>(py, pw1 + (size_t)l*FFc*Hc, b1 + l*FFc,
                                                   pff, Hc, FFc);
        cp_gemm<2><<<gproj, 256, CPG_SMEM>>>(pff, pw2 + (size_t)l*Hc*FFc, b2 + l*Hc,
                                             ph, ph, FFc, Hc);
    }
    ln_kernel<<<Mrows, 256>>>(ph, flng, flnb, (float*)d_out, 0);
}

// round 16
// speedup vs baseline: 1.1834x; 1.1834x over previous
#include <cuda_runtime.h>
#include <cuda_bf16.h>
#include <math.h>

// Problem constants
#define Lc 4
#define Bc 16
#define Sc 512
#define Hc 768
#define NHc 12
#define FFc 3072
#define Dc 64
#define Mrows (Bc*Sc)          // 8192
#define BHc (Bc*NHc)           // 192
#define QKVS 2304              // packed qkv row stride

// ---------------- scratch (device globals; no allocations allowed) -------------
__device__ float g_h [Mrows*Hc];
__device__ float g_y [Mrows*Hc];
__device__ float g_ao[Mrows*Hc];
__device__ float g_ff[(size_t)Mrows*FFc];   // holds packed qkv early in layer
__device__ float g_wqkvT[(size_t)Lc*3*Hc*Hc];  // [L][2304][768]
__device__ float g_woT  [(size_t)Lc*Hc*Hc];    // [L][768][768]
__device__ float g_w1T  [(size_t)Lc*FFc*Hc];   // [L][3072][768]
__device__ float g_w2T  [(size_t)Lc*Hc*FFc];   // [L][768][3072]
__device__ float g_bqkv [Lc*3*Hc];

// ---------------- reductions -------------
__device__ __forceinline__ float warpSum(float v){
#pragma unroll
    for (int o=16;o>0;o>>=1) v += __shfl_xor_sync(0xffffffffu, v, o);
    return v;
}
__device__ float blockSum(float v){
    __shared__ float sh[8];
    __syncthreads();
    v = warpSum(v);
    int lane = threadIdx.x & 31, w = threadIdx.x >> 5;
    if (lane==0) sh[w] = v;
    __syncthreads();
    int nw = blockDim.x >> 5;
    float r = 0.f;
#pragma unroll 8
    for (int i=0;i<nw;i++) if (i < nw) r += sh[i];
    return r;
}

// ---------------- helpers -------------
__device__ __forceinline__ unsigned f2tf32(float x){
    unsigned r; asm("cvt.rna.tf32.f32 %0, %1;" : "=r"(r) : "f"(x)); return r;
}
__device__ __forceinline__ float tf32f(float x){
    return __uint_as_float(f2tf32(x));
}
__device__ __forceinline__ void ldsm4(unsigned* d, const float* p){
    unsigned a = (unsigned)__cvta_generic_to_shared(p);
    asm volatile("ldmatrix.sync.aligned.m8n8.x4.shared.b16 {%0,%1,%2,%3}, [%4];"
                 : "=r"(d[0]),"=r"(d[1]),"=r"(d[2]),"=r"(d[3]) : "r"(a));
}
__device__ __forceinline__ void mma_tf32(float* c, const unsigned* a, unsigned b0, unsigned b1){
    asm volatile("mma.sync.aligned.m16n8k8.row.col.f32.tf32.tf32.f32 "
                 "{%0,%1,%2,%3}, {%4,%5,%6,%7}, {%8,%9}, {%0,%1,%2,%3};"
                 : "+f"(c[0]),"+f"(c[1]),"+f"(c[2]),"+f"(c[3])
                 : "r"(a[0]),"r"(a[1]),"r"(a[2]),"r"(a[3]), "r"(b0),"r"(b1));
}
__device__ __forceinline__ float gelu_exact(float x){
    return 0.5f * x * (1.0f + erff(x * 0.70710678118654752f));
}
__device__ __forceinline__ void cpa16(unsigned dst, const void* src){
    asm volatile("cp.async.cg.shared.global [%0], [%1], 16;" :: "r"(dst), "l"(src));
}
__device__ __forceinline__ void cpa_commit(){
    asm volatile("cp.async.commit_group;" ::: "memory");
}
template<int W> __device__ __forceinline__ void cpa_wait(){
    asm volatile("cp.async.wait_group %0;" :: "n"(W) : "memory");
}

// ---------------- LayerNorm ----
__global__ void ln_kernel(const float* __restrict__ x, const float* __restrict__ g,
                          const float* __restrict__ b, float* __restrict__ o, int rnd){
    int row = blockIdx.x;
    const float* p = x + (size_t)row*Hc;
    int t = threadIdx.x;
    float v0 = p[t], v1 = p[t+256], v2 = p[t+512];
    float s  = blockSum(v0+v1+v2);
    float m  = s * (1.0f/768.0f);
    float d0 = v0-m, d1 = v1-m, d2 = v2-m;
    float vs = blockSum(d0*d0 + d1*d1 + d2*d2);
    float inv = rsqrtf(vs * (1.0f/768.0f) + 1e-5f);
    float* q = o + (size_t)row*Hc;
    float r0 = d0*inv*g[t]     + b[t];
    float r1 = d1*inv*g[t+256] + b[t+256];
    float r2 = d2*inv*g[t+512] + b[t+512];
    if (rnd){ r0 = tf32f(r0); r1 = tf32f(r1); r2 = tf32f(r2); }
    q[t] = r0; q[t+256] = r1; q[t+512] = r2;
}

// ---------------- weight transpose + tf32 round ----
__global__ void transpose_w(const float* __restrict__ in, float* __restrict__ out,
                            int K, int N, int noff, int OS,
                            size_t inL, size_t outL){
    __shared__ float t[32][33];
    int l = blockIdx.z;
    in  += (size_t)l*inL;
    out += (size_t)l*outL;
    int nb = blockIdx.x*32, kb = blockIdx.y*32;
    int tx = threadIdx.x, ty = threadIdx.y;   // 32 x 8
#pragma unroll
    for (int j=0;j<4;j++)
        t[ty+j*8][tx] = in[(size_t)(kb+ty+j*8)*N + nb+tx];
    __syncthreads();
#pragma unroll
    for (int j=0;j<4;j++)
        out[(size_t)(noff+nb+ty+j*8)*OS + kb+tx] = tf32f(t[tx][ty+j*8]);
}

// ---------------- pack qkv bias ----
__global__ void pack_bias(const float* __restrict__ bq, const float* __restrict__ bk,
                          const float* __restrict__ bv, float* __restrict__ o){
    int i = blockIdx.x*256 + threadIdx.x;
    if (i < Lc*QKVS){
        int l = i/QKVS, j = i%QKVS;
        float v = (j<768) ? bq[l*768+j] : (j<1536 ? bk[l*768+j-768] : bv[l*768+j-1536]);
        o[i] = v;
    }
}

// ---------------- cp.async tf32 GEMM: 128x128 tile, warp 64x32 (R11 proven) ----
#define PADt 20
#define STGF (128*PADt)
#define CPG_SMEM (3*2*STGF*4)   // 61440 B
template<int EPI>
__global__ __launch_bounds__(256,2) void cp_gemm(
        const float* __restrict__ A, const float* __restrict__ Bt,
        const float* __restrict__ bias, const float* __restrict__ R,
        float* __restrict__ C, int K, int N){
    extern __shared__ float sms[];
    int tid = threadIdx.x;
    int bm = blockIdx.y*128, bn = blockIdx.x*128;
    int warp = tid>>5, lane = tid&31;
    int wm = (warp>>2)*64, wn = (warp&3)*32;

    int id0 = tid*2, id1 = tid*2+1;
    int r0 = id0>>2, s0g = id0&3, r1 = id1>>2, s1g = id1&3;
    const float* Ap0 = A + (size_t)(bm+r0)*K + s0g*4;
    const float* Ap1 = A + (size_t)(bm+r1)*K + s1g*4;
    const float* Bp0 = Bt + (size_t)(bn+r0)*K + s0g*4;
    const float* Bp1 = Bt + (size_t)(bn+r1)*K + s1g*4;
    unsigned sbase = (unsigned)__cvta_generic_to_shared(sms);
    unsigned oa0 = (r0*PADt + s0g*4)*4, oa1 = (r1*PADt + s1g*4)*4;

    int g = lane>>3, lr = lane&7;
    int a_row = wm + lr + (g&1)*8;
    int a_colq = (g>>1)*4;
    int b_row = wn + lr + (g>>1)*8;
    int b_colq = (g&1)*4;

    float acc[16][4];
#pragma unroll
    for (int i=0;i<16;i++){ acc[i][0]=0.f; acc[i][1]=0.f; acc[i][2]=0.f; acc[i][3]=0.f; }

    int nch = K >> 4;
#pragma unroll
    for (int st=0; st<2; st++){
        unsigned base = sbase + st*(2*STGF*4);
        int k0 = st*16;
        cpa16(base + oa0, Ap0 + k0);
        cpa16(base + oa1, Ap1 + k0);
        cpa16(base + STGF*4 + oa0, Bp0 + k0);
        cpa16(base + STGF*4 + oa1, Bp1 + k0);
        cpa_commit();
    }

#pragma unroll 1
    for (int it=0; it<nch; ++it){
        int st = it - (it/3)*3;
        if (it+2 < nch) cpa_wait<1>(); else cpa_wait<0>();
        __syncthreads();
        const float* as = sms + st*(2*STGF);
        const float* bs = as + STGF;
#pragma unroll
        for (int kc=0; kc<16; kc+=8){
            unsigned af[4][4];
#pragma unroll
            for (int mt=0; mt<4; mt++)
                ldsm4(af[mt], &as[(a_row + mt*16)*PADt + kc + a_colq]);
            unsigned bf[2][4];
#pragma unroll
            for (int np=0; np<2; np++)
                ldsm4(bf[np], &bs[(b_row + np*16)*PADt + kc + b_colq]);
#pragma unroll
            for (int mt=0; mt<4; mt++)
#pragma unroll
                for (int nt=0; nt<4; nt++)
                    mma_tf32(acc[mt*4+nt], af[mt], bf[nt>>1][(nt&1)*2], bf[nt>>1][(nt&1)*2+1]);
        }
        if (it+2 < nch){
            int st2 = (it+2) - ((it+2)/3)*3;
            unsigned base = sbase + st2*(2*STGF*4);
            int k0 = (it+2)*16;
            cpa16(base + oa0, Ap0 + k0);
            cpa16(base + oa1, Ap1 + k0);
            cpa16(base + STGF*4 + oa0, Bp0 + k0);
            cpa16(base + STGF*4 + oa1, Bp1 + k0);
            cpa_commit();
        }
    }

    int cr = lane>>2, cc = (lane&3)*2;
#pragma unroll
    for (int nt=0; nt<4; nt++){
        int col = bn + wn + nt*8 + cc;
        float2 bv = *(const float2*)(bias + col);
#pragma unroll
        for (int mt=0; mt<4; mt++){
            int row0 = bm + wm + mt*16 + cr;
            float* a4 = acc[mt*4+nt];
#pragma unroll
            for (int half=0; half<2; half++){
                int row = row0 + half*8;
                float2 r;
                r.x = a4[half*2+0] + bv.x;
                r.y = a4[half*2+1] + bv.y;
                if (EPI==1){
                    r.x = tf32f(gelu_exact(r.x));
                    r.y = tf32f(gelu_exact(r.y));
                }
                if (EPI==2){
                    float2 rr = *(const float2*)(R + (size_t)row*N + col);
                    r.x += rr.x; r.y += rr.y;
                }
                *(float2*)(C + (size_t)row*N + col) = r;
            }
        }
    }
}

// ---------------- fused flash attention: per (bh, 128-s-block) -------------
// S = 0.125*Q K^T + bias ; online softmax ; O = P V ; O /= l ; tf32-round out.
#define PADQ 68
#define FA_FLOATS (384*PADQ + 3*128 + 2*256)
#define FA_SMEM (FA_FLOATS*4)
__global__ __launch_bounds__(256) void fused_attn(
        const float* __restrict__ qkv, const float* __restrict__ bias,
        float* __restrict__ o){
    extern __shared__ float sm[];
    float* Qs   = sm;                    // [128][68] (s, d)
    float* Ks   = Qs + 128*PADQ;         // [64][68]  (t, d)
    float* Vs   = Ks + 64*PADQ;          // [64][68]  (d, t)
    float* Ps   = Vs + 64*PADQ;          // [128][68] (s, t)
    float* mrow = Ps + 128*PADQ;         // [128]
    float* lrow = mrow + 128;            // [128]
    float* srow = lrow + 128;            // [128]
    float* redm = srow + 128;            // [128][2]
    float* reds = redm + 256;            // [128][2]

    int bh = blockIdx.y;
    int b = bh / NHc, h = bh % NHc;
    int s0 = blockIdx.x*128;
    int tid = threadIdx.x, warp = tid>>5, lane = tid&31;
    int wm = (warp>>1)*32, wn = (warp&1)*32;   // warp grid 4(s) x 2(t|d)
    int widx = warp&1;
    int g = lane>>3, lr = lane&7;
    int a_row = wm + lr + (g&1)*8;
    int a_colq = (g>>1)*4;
    int b_row = wn + lr + (g>>1)*8;
    int b_colq = (g&1)*4;
    int q4 = lane>>2, cq = (lane&3)*2;

    // load Q tile (once)
    {
        int row = tid>>1, cb = (tid&1)*32;
        const float* qp = qkv + (size_t)(b*Sc + s0 + row)*QKVS + h*Dc + cb;
        float* dq = &Qs[row*PADQ + cb];
#pragma unroll
        for (int z=0; z<8; z++){
            float4 a = *(const float4*)(qp + z*4);
            dq[z*4+0]=tf32f(a.x); dq[z*4+1]=tf32f(a.y);
            dq[z*4+2]=tf32f(a.z); dq[z*4+3]=tf32f(a.w);
        }
    }
    if (tid < 128){ mrow[tid] = -3.402823466e38f; lrow[tid] = 0.f; }

    float acc_o[8][4];
#pragma unroll
    for (int i=0;i<8;i++){ acc_o[i][0]=0.f; acc_o[i][1]=0.f; acc_o[i][2]=0.f; acc_o[i][3]=0.f; }

    int kl = tid>>2, kcb = (tid&3)*16;   // K/V chunk load mapping

    for (int t0=0; t0<Sc; t0+=64){
        __syncthreads();   // prev iter done with Ks/Vs (and Q load on iter 0)
        // load K chunk [64 t][64 d], V chunk transposed [64 d][64 t]
        {
            const float* kp = qkv + (size_t)(b*Sc + t0 + kl)*QKVS + h*Dc + 768 + kcb;
            float* dk = &Ks[kl*PADQ + kcb];
#pragma unroll
            for (int z=0; z<4; z++){
                float4 c = *(const float4*)(kp + z*4);
                dk[z*4+0]=tf32f(c.x); dk[z*4+1]=tf32f(c.y);
                dk[z*4+2]=tf32f(c.z); dk[z*4+3]=tf32f(c.w);
            }
            const float* vp = qkv + (size_t)(b*Sc + t0 + kl)*QKVS + h*Dc + 1536 + kcb;
#pragma unroll
            for (int z=0; z<4; z++){
                float4 c = *(const float4*)(vp + z*4);
                Vs[(kcb+z*4+0)*PADQ + kl]=tf32f(c.x);
                Vs[(kcb+z*4+1)*PADQ + kl]=tf32f(c.y);
                Vs[(kcb+z*4+2)*PADQ + kl]=tf32f(c.z);
                Vs[(kcb+z*4+3)*PADQ + kl]=tf32f(c.w);
            }
        }
        __syncthreads();

        // S = Q K^T (warp 32s x 32t)
        float acc_s[8][4];
#pragma unroll
        for (int i=0;i<8;i++){ acc_s[i][0]=0.f; acc_s[i][1]=0.f; acc_s[i][2]=0.f; acc_s[i][3]=0.f; }
#pragma unroll
        for (int kc=0; kc<64; kc+=8){
            unsigned af[2][4];
#pragma unroll
            for (int mt=0; mt<2; mt++)
                ldsm4(af[mt], &Qs[(a_row + mt*16)*PADQ + kc + a_colq]);
            unsigned bf[2][4];
#pragma unroll
            for (int np=0; np<2; np++)
                ldsm4(bf[np], &Ks[(b_row + np*16)*PADQ + kc + b_colq]);
#pragma unroll
            for (int mt=0; mt<2; mt++)
#pragma unroll
                for (int nt=0; nt<4; nt++)
                    mma_tf32(acc_s[mt*4+nt], af[mt], bf[nt>>1][(nt&1)*2], bf[nt>>1][(nt&1)*2+1]);
        }

        // scale + bias, per-row max (quad-reduce)
        float rmax[2][2];
        rmax[0][0]=rmax[0][1]=rmax[1][0]=rmax[1][1] = -3.402823466e38f;
#pragma unroll
        for (int mt=0; mt<2; mt++){
            int sr0 = s0 + wm + mt*16 + q4;
#pragma unroll
            for (int nt=0; nt<4; nt++){
                int col = t0 + wn + nt*8 + cq;
                float2 bi0 = *(const float2*)(bias + ((size_t)bh*Sc + sr0)*Sc + col);
                float2 bi1 = *(const float2*)(bias + ((size_t)bh*Sc + sr0+8)*Sc + col);
                float* a4 = acc_s[mt*4+nt];
                a4[0] = fmaf(a4[0], 0.125f, bi0.x);
                a4[1] = fmaf(a4[1], 0.125f, bi0.y);
                a4[2] = fmaf(a4[2], 0.125f, bi1.x);
                a4[3] = fmaf(a4[3], 0.125f, bi1.y);
                rmax[mt][0] = fmaxf(rmax[mt][0], fmaxf(a4[0], a4[1]));
                rmax[mt][1] = fmaxf(rmax[mt][1], fmaxf(a4[2], a4[3]));
            }
#pragma unroll
            for (int hf=0; hf<2; hf++){
                rmax[mt][hf] = fmaxf(rmax[mt][hf], __shfl_xor_sync(0xffffffffu, rmax[mt][hf], 1));
                rmax[mt][hf] = fmaxf(rmax[mt][hf], __shfl_xor_sync(0xffffffffu, rmax[mt][hf], 2));
            }
        }
        if ((lane&3)==0){
#pragma unroll
            for (int mt=0; mt<2; mt++){
                redm[(wm+mt*16+q4)*2 + widx]   = rmax[mt][0];
                redm[(wm+mt*16+q4+8)*2 + widx] = rmax[mt][1];
            }
        }
        __syncthreads();
        if (tid < 128){
            float mo = mrow[tid];
            float nm = fmaxf(mo, fmaxf(redm[tid*2], redm[tid*2+1]));
            mrow[tid] = nm;
            srow[tid] = __expf(mo - nm);
        }
        __syncthreads();

        // exp, Ps store, row sums
        float rsum[2][2] = {{0.f,0.f},{0.f,0.f}};
#pragma unroll
        for (int mt=0; mt<2; mt++){
            int r0i = wm + mt*16 + q4;
            float nm0 = mrow[r0i], nm1 = mrow[r0i+8];
#pragma unroll
            for (int nt=0; nt<4; nt++){
                float* a4 = acc_s[mt*4+nt];
                float p0 = __expf(a4[0]-nm0), p1 = __expf(a4[1]-nm0);
                float p2 = __expf(a4[2]-nm1), p3 = __expf(a4[3]-nm1);
                rsum[mt][0] += p0+p1; rsum[mt][1] += p2+p3;
                int col = wn + nt*8 + cq;
                float2 w0; w0.x = p0; w0.y = p1;
                float2 w1; w1.x = p2; w1.y = p3;
                *(float2*)&Ps[r0i*PADQ + col] = w0;
                *(float2*)&Ps[(r0i+8)*PADQ + col] = w1;
            }
#pragma unroll
            for (int hf=0; hf<2; hf++){
                rsum[mt][hf] += __shfl_xor_sync(0xffffffffu, rsum[mt][hf], 1);
                rsum[mt][hf] += __shfl_xor_sync(0xffffffffu, rsum[mt][hf], 2);
            }
        }
        if ((lane&3)==0){
#pragma unroll
            for (int mt=0; mt<2; mt++){
                reds[(wm+mt*16+q4)*2 + widx]   = rsum[mt][0];
                reds[(wm+mt*16+q4+8)*2 + widx] = rsum[mt][1];
            }
        }
        __syncthreads();
        if (tid < 128)
            lrow[tid] = lrow[tid]*srow[tid] + reds[tid*2] + reds[tid*2+1];

        // O rescale + P@V accumulate (warp 32s x 32d)
#pragma unroll
        for (int mt=0; mt<2; mt++){
            int r0i = wm + mt*16 + q4;
            float sc0 = srow[r0i], sc1 = srow[r0i+8];
#pragma unroll
            for (int nt=0; nt<4; nt++){
                float* a4 = acc_o[mt*4+nt];
                a4[0]*=sc0; a4[1]*=sc0; a4[2]*=sc1; a4[3]*=sc1;
            }
        }
#pragma unroll
        for (int kc=0; kc<64; kc+=8){
            unsigned af[2][4];
#pragma unroll
            for (int mt=0; mt<2; mt++)
                ldsm4(af[mt], &Ps[(a_row + mt*16)*PADQ + kc + a_colq]);
            unsigned bf[2][4];
#pragma unroll
            for (int np=0; np<2; np++)
                ldsm4(bf[np], &Vs[(b_row + np*16)*PADQ + kc + b_colq]);
#pragma unroll
            for (int mt=0; mt<2; mt++)
#pragma unroll
                for (int nt=0; nt<4; nt++)
                    mma_tf32(acc_o[mt*4+nt], af[mt], bf[nt>>1][(nt&1)*2], bf[nt>>1][(nt&1)*2+1]);
        }
    }
    __syncthreads();   // lrow final

    // output: O /= l, tf32-round (feeds Wo GEMM as A)
#pragma unroll
    for (int mt=0; mt<2; mt++){
        int r0i = wm + mt*16 + q4;
        float li0 = 1.0f/lrow[r0i], li1 = 1.0f/lrow[r0i+8];
        int sr0 = s0 + r0i;
#pragma unroll
        for (int nt=0; nt<4; nt++){
            int dcol = wn + nt*8 + cq;
            float* a4 = acc_o[mt*4+nt];
            float2 w0; w0.x = tf32f(a4[0]*li0); w0.y = tf32f(a4[1]*li0);
            float2 w1; w1.x = tf32f(a4[2]*li1); w1.y = tf32f(a4[3]*li1);
            *(float2*)(o + ((size_t)(b*Sc + sr0)*NHc + h)*Dc + dcol) = w0;
            *(float2*)(o + ((size_t)(b*Sc + sr0+8)*NHc + h)*Dc + dcol) = w1;
        }
    }
}

// ---------------- launch -------------
extern "C" void kernel_launch(void* const* d_in, const int* in_sizes, int n_in,
                              void* d_out, int out_size){
    const float* x    = (const float*)d_in[0];
    const float* ab   = (const float*)d_in[1];
    const float* ln1g = (const float*)d_in[2];
    const float* ln1b = (const float*)d_in[3];
    const float* wq   = (const float*)d_in[4];
    const float* bq   = (const float*)d_in[5];
    const float* wk   = (const float*)d_in[6];
    const float* bk   = (const float*)d_in[7];
    const float* wv   = (const float*)d_in[8];
    const float* bv   = (const float*)d_in[9];
    const float* wo   = (const float*)d_in[10];
    const float* bo   = (const float*)d_in[11];
    const float* ln2g = (const float*)d_in[12];
    const float* ln2b = (const float*)d_in[13];
    const float* w1   = (const float*)d_in[14];
    const float* b1   = (const float*)d_in[15];
    const float* w2   = (const float*)d_in[16];
    const float* b2   = (const float*)d_in[17];
    const float* flng = (const float*)d_in[18];
    const float* flnb = (const float*)d_in[19];

    float *ph, *py, *pao, *pff, *pwqkv, *pwo, *pw1, *pw2, *pbqkv;
    cudaGetSymbolAddress((void**)&ph,   g_h);
    cudaGetSymbolAddress((void**)&py,   g_y);
    cudaGetSymbolAddress((void**)&pao,  g_ao);
    cudaGetSymbolAddress((void**)&pff,  g_ff);
    cudaGetSymbolAddress((void**)&pwqkv,g_wqkvT);
    cudaGetSymbolAddress((void**)&pwo,  g_woT);
    cudaGetSymbolAddress((void**)&pw1,  g_w1T);
    cudaGetSymbolAddress((void**)&pw2,  g_w2T);
    cudaGetSymbolAddress((void**)&pbqkv,g_bqkv);

    static int smem_set = 0;
    if (!smem_set){
        cudaFuncSetAttribute(fused_attn, cudaFuncAttributeMaxDynamicSharedMemorySize, FA_SMEM);
        cudaFuncSetAttribute(cp_gemm<0>, cudaFuncAttributeMaxDynamicSharedMemorySize, CPG_SMEM);
        cudaFuncSetAttribute(cp_gemm<1>, cudaFuncAttributeMaxDynamicSharedMemorySize, CPG_SMEM);
        cudaFuncSetAttribute(cp_gemm<2>, cudaFuncAttributeMaxDynamicSharedMemorySize, CPG_SMEM);
        smem_set = 1;
    }

    cudaMemcpyAsync(ph, x, (size_t)Mrows*Hc*sizeof(float), cudaMemcpyDeviceToDevice, 0);

    // ---- weight prep ----
    dim3 tb(32,8);
    transpose_w<<<dim3(Hc/32, Hc/32, Lc), tb>>>(wq, pwqkv, Hc, Hc, 0,    Hc, (size_t)Hc*Hc, (size_t)QKVS*Hc);
    transpose_w<<<dim3(Hc/32, Hc/32, Lc), tb>>>(wk, pwqkv, Hc, Hc, 768,  Hc, (size_t)Hc*Hc, (size_t)QKVS*Hc);
    transpose_w<<<dim3(Hc/32, Hc/32, Lc), tb>>>(wv, pwqkv, Hc, Hc, 1536, Hc, (size_t)Hc*Hc, (size_t)QKVS*Hc);
    transpose_w<<<dim3(Hc/32, Hc/32, Lc), tb>>>(wo, pwo,   Hc, Hc, 0,    Hc, (size_t)Hc*Hc, (size_t)Hc*Hc);
    transpose_w<<<dim3(FFc/32, Hc/32, Lc), tb>>>(w1, pw1,  Hc, FFc, 0,   Hc, (size_t)Hc*FFc, (size_t)FFc*Hc);
    transpose_w<<<dim3(Hc/32, FFc/32, Lc), tb>>>(w2, pw2,  FFc, Hc, 0,  FFc, (size_t)FFc*Hc, (size_t)Hc*FFc);
    pack_bias<<<(Lc*QKVS+255)/256, 256>>>(bq, bk, bv, pbqkv);

    dim3 gqkv(QKVS/128, Mrows/128);     // 18 x 64
    dim3 gproj(Hc/128, Mrows/128);      // 6 x 64
    dim3 gffn1(FFc/128, Mrows/128);     // 24 x 64
    dim3 gfa(4, BHc);

    for (int l=0; l<Lc; l++){
        ln_kernel<<<Mrows, 256>>>(ph, ln1g + l*Hc, ln1b + l*Hc, py, 1);
        cp_gemm<0><<<gqkv, 256, CPG_SMEM>>>(py, pwqkv + (size_t)l*QKVS*Hc, pbqkv + l*QKVS,
                                            nullptr, pff, Hc, QKVS);
        fused_attn<<<gfa, 256, FA_SMEM>>>(pff, ab, pao);
        cp_gemm<2><<<gproj, 256, CPG_SMEM>>>(pao, pwo + (size_t)l*Hc*Hc, bo + l*Hc,
                                             ph, ph, Hc, Hc);
        ln_kernel<<<Mrows, 256>>>(ph, ln2g + l*Hc, ln2b + l*Hc, py, 1);
        cp_gemm<1><<<gffn1, 256, CPG_SMEM>>>(py, pw1 + (size_t)l*FFc*Hc, b1 + l*FFc,
                                             nullptr, pff, Hc, FFc);
        cp_gemm<2><<<gproj, 256, CPG_SMEM>>>(pff, pw2 + (size_t)l*Hc*FFc, b2 + l*Hc,
                                             ph, ph, FFc, Hc);
    }
    ln_kernel<<<Mrows, 256>>>(ph, flng, flnb, (float*)d_out, 0);
}